// round 2
// baseline (speedup 1.0000x reference)
#include <cuda_runtime.h>

// out = relu(cos(x+theta) @ W1 + b1) @ W2 + b2
// x: [B*S, 8] fp32, W1: [8,32], W2: [32,8], out: [B*S, 8] fp32
//
// Strategy: packed f32x2 FFMA (Blackwell PTX fma.rn.f32x2) — 2 rows per
// vector lane, 2 row-pairs per thread (4 rows/thread). Weights are
// pre-broadcast into shared as {w,w} 64-bit pairs so each LDS.128 feeds
// two FFMA2 ops and is reused across both row-pairs.

using u64 = unsigned long long;

__device__ __forceinline__ u64 pack2(float lo, float hi) {
    u64 r;
    asm("mov.b64 %0, {%1, %2};" : "=l"(r) : "f"(lo), "f"(hi));
    return r;
}

__device__ __forceinline__ float2 unpack2(u64 v) {
    float2 f;
    asm("mov.b64 {%0, %1}, %2;" : "=f"(f.x), "=f"(f.y) : "l"(v));
    return f;
}

__device__ __forceinline__ u64 ffma2(u64 a, u64 b, u64 c) {
    u64 d;
    asm("fma.rn.f32x2 %0, %1, %2, %3;" : "=l"(d) : "l"(a), "l"(b), "l"(c));
    return d;
}

constexpr int E = 8;
constexpr int F = 32;
constexpr int PAIRS = 2;                 // f32x2 row-pairs per thread
constexpr int ROWS_PER_THREAD = 2 * PAIRS; // 4 rows/thread
constexpr int BLOCK = 128;

__global__ __launch_bounds__(BLOCK)
void ffq_kernel(const float* __restrict__ x,
                const float* __restrict__ theta,
                const float* __restrict__ w1,
                const float* __restrict__ b1,
                const float* __restrict__ w2,
                const float* __restrict__ b2,
                float* __restrict__ out,
                long nrows)
{
    __shared__ __align__(16) u64 s_w1[E * F];  // {w,w} broadcast pairs
    __shared__ __align__(16) u64 s_w2[F * E];
    __shared__ __align__(16) u64 s_b1[F];
    __shared__ __align__(16) u64 s_b2[E];
    __shared__ float s_th[E];

    const int t = threadIdx.x;

    // Stage broadcast-packed weights once per CTA.
    for (int i = t; i < E * F; i += BLOCK) { float w = w1[i]; s_w1[i] = pack2(w, w); }
    for (int i = t; i < F * E; i += BLOCK) { float w = w2[i]; s_w2[i] = pack2(w, w); }
    if (t < F) { float v = b1[t]; s_b1[t] = pack2(v, v); }
    if (t < E) {
        float v = b2[t]; s_b2[t] = pack2(v, v);
        s_th[t] = theta[t];
    }
    __syncthreads();

    const long row0 = ((long)blockIdx.x * BLOCK + t) * ROWS_PER_THREAD;
    if (row0 >= nrows) return;

    float th[E];
#pragma unroll
    for (int i = 0; i < E; i++) th[i] = s_th[i];

    // ---- Load x rows (4 rows x 8 floats = 8x float4, fully coalesced per warp)
    const float4* xv = (const float4*)(x + row0 * E);
    float xr[ROWS_PER_THREAD][E];
#pragma unroll
    for (int r = 0; r < ROWS_PER_THREAD; r++) {
        float4 lo = xv[2 * r + 0];
        float4 hi = xv[2 * r + 1];
        xr[r][0] = lo.x; xr[r][1] = lo.y; xr[r][2] = lo.z; xr[r][3] = lo.w;
        xr[r][4] = hi.x; xr[r][5] = hi.y; xr[r][6] = hi.z; xr[r][7] = hi.w;
    }

    // ---- q = cos(x + theta), packed as {row 2p, row 2p+1}
    u64 q[PAIRS][E];
#pragma unroll
    for (int p = 0; p < PAIRS; p++) {
#pragma unroll
        for (int i = 0; i < E; i++) {
            float a = __cosf(xr[2 * p + 0][i] + th[i]);
            float b = __cosf(xr[2 * p + 1][i] + th[i]);
            q[p][i] = pack2(a, b);
        }
    }

    // ---- Layer 1: h = q @ W1 + b1   (8 -> 32)
    u64 h[PAIRS][F];
#pragma unroll
    for (int j = 0; j < F; j++) {
        u64 bj = s_b1[j];
        h[0][j] = bj;
        h[1][j] = bj;
    }
#pragma unroll
    for (int i = 0; i < E; i++) {
#pragma unroll
        for (int j = 0; j < F; j++) {
            u64 w = s_w1[i * F + j];
            h[0][j] = ffma2(q[0][i], w, h[0][j]);
            h[1][j] = ffma2(q[1][i], w, h[1][j]);
        }
    }

    // ---- ReLU (per 32-bit half; register-pair halves alias the floats)
#pragma unroll
    for (int p = 0; p < PAIRS; p++) {
#pragma unroll
        for (int j = 0; j < F; j++) {
            float2 f = unpack2(h[p][j]);
            f.x = fmaxf(f.x, 0.0f);
            f.y = fmaxf(f.y, 0.0f);
            h[p][j] = pack2(f.x, f.y);
        }
    }

    // ---- Layer 2: out = h @ W2 + b2   (32 -> 8)
    u64 o[PAIRS][E];
#pragma unroll
    for (int e = 0; e < E; e++) {
        u64 be = s_b2[e];
        o[0][e] = be;
        o[1][e] = be;
    }
#pragma unroll
    for (int j = 0; j < F; j++) {
#pragma unroll
        for (int e = 0; e < E; e++) {
            u64 w = s_w2[j * E + e];
            o[0][e] = ffma2(h[0][j], w, o[0][e]);
            o[1][e] = ffma2(h[1][j], w, o[1][e]);
        }
    }

    // ---- Store 4 rows (8x STG.128)
    float4* ov = (float4*)(out + row0 * E);
#pragma unroll
    for (int p = 0; p < PAIRS; p++) {
        float2 f[E];
#pragma unroll
        for (int e = 0; e < E; e++) f[e] = unpack2(o[p][e]);
        // row 2p  = lo halves, row 2p+1 = hi halves
        ov[4 * p + 0] = make_float4(f[0].x, f[1].x, f[2].x, f[3].x);
        ov[4 * p + 1] = make_float4(f[4].x, f[5].x, f[6].x, f[7].x);
        ov[4 * p + 2] = make_float4(f[0].y, f[1].y, f[2].y, f[3].y);
        ov[4 * p + 3] = make_float4(f[4].y, f[5].y, f[6].y, f[7].y);
    }
}

extern "C" void kernel_launch(void* const* d_in, const int* in_sizes, int n_in,
                              void* d_out, int out_size)
{
    const float* x     = (const float*)d_in[0];
    const float* theta = (const float*)d_in[1];
    const float* w1    = (const float*)d_in[2];
    const float* b1    = (const float*)d_in[3];
    const float* w2    = (const float*)d_in[4];
    const float* b2    = (const float*)d_in[5];
    float* out = (float*)d_out;

    const long nrows = (long)in_sizes[0] / E;  // 524288
    const long nthreads = (nrows + ROWS_PER_THREAD - 1) / ROWS_PER_THREAD;
    const int grid = (int)((nthreads + BLOCK - 1) / BLOCK);

    ffq_kernel<<<grid, BLOCK>>>(x, theta, w1, b1, w2, b2, out, nrows);
}